// round 16
// baseline (speedup 1.0000x reference)
#include <cuda_runtime.h>
#include <cuda_fp16.h>
#include <math.h>
#include <cstdint>

#define D_MODEL 1024
#define N_HEADS 16
#define D_KH    64
#define BATCH   4
#define SEQ     2048
#define MROWS   (BATCH*SEQ)   // 8192

// ---------------- scratch (device globals: allocation-free rule) ------------
__device__ __half g_Q16[(size_t)BATCH*N_HEADS*SEQ*D_KH];
__device__ __half g_K16[(size_t)BATCH*N_HEADS*SEQ*D_KH];
__device__ __half g_V16[(size_t)BATCH*N_HEADS*SEQ*D_KH];
__device__ __half g_O16[(size_t)MROWS*D_MODEL];
__device__ __half g_X16[(size_t)MROWS*D_MODEL];
__device__ __half g_Wq16[(size_t)D_MODEL*D_MODEL];
__device__ __half g_Wk16[(size_t)D_MODEL*D_MODEL];
__device__ __half g_Wv16[(size_t)D_MODEL*D_MODEL];
__device__ __half g_Wo16[(size_t)D_MODEL*D_MODEL];
__device__ int    g_Mflag[(SEQ/128)*(SEQ/64)];

// =============================== PTX helpers ================================
__device__ __forceinline__ uint32_t smem_u32(const void* p) {
    uint32_t a;
    asm("{ .reg .u64 t; cvta.to.shared.u64 t, %1; cvt.u32.u64 %0, t; }" : "=r"(a) : "l"(p));
    return a;
}
__device__ __forceinline__ float ex2f(float x) {
    float y;
    asm("ex2.approx.f32 %0, %1;" : "=f"(y) : "f"(x));
    return y;
}
__device__ __forceinline__ uint32_t f2h2(float lo, float hi) {
    uint32_t r;
    asm("cvt.rn.f16x2.f32 %0, %2, %1;" : "=r"(r) : "f"(lo), "f"(hi));
    return r;
}
__device__ __forceinline__ void mma_f16(float* c,
                                        uint32_t a0, uint32_t a1, uint32_t a2, uint32_t a3,
                                        uint32_t b0, uint32_t b1) {
    asm volatile(
        "mma.sync.aligned.m16n8k16.row.col.f32.f16.f16.f32 "
        "{%0,%1,%2,%3}, {%4,%5,%6,%7}, {%8,%9}, {%0,%1,%2,%3};"
        : "+f"(c[0]), "+f"(c[1]), "+f"(c[2]), "+f"(c[3])
        : "r"(a0), "r"(a1), "r"(a2), "r"(a3), "r"(b0), "r"(b1));
}
#define CP_ASYNC16(sa, ga) \
    asm volatile("cp.async.cg.shared.global [%0], [%1], 16;" :: "r"(sa), "l"(ga) : "memory")
#define CP_COMMIT() asm volatile("cp.async.commit_group;" ::: "memory")
#define CP_WAIT1()  asm volatile("cp.async.wait_group 1;" ::: "memory")
#define CP_WAIT0()  asm volatile("cp.async.wait_group 0;" ::: "memory")

__device__ __forceinline__ int p8(int p) { return (p < 4) ? 2 * p : 2 * (p - 4) + 1; }
__device__ __forceinline__ int perm16(int d) { return p8(d >> 1) * 2 + (d & 1); }
__device__ __forceinline__ int csw8(int c, int r) {
    return (((c >> 1) ^ (r & 3)) << 1) | (c & 1);
}

// ---------------- prepass kernels -------------------------------------------
__device__ __forceinline__ void cvt_perm16(const float4* in, uint4* out, size_t i) {
    float4 v0 = in[4 * i], v1 = in[4 * i + 1], v2 = in[4 * i + 2], v3 = in[4 * i + 3];
    uint32_t h0 = f2h2(v0.x, v0.y);
    uint32_t h2 = f2h2(v0.z, v0.w);
    uint32_t h4 = f2h2(v1.x, v1.y);
    uint32_t h6 = f2h2(v1.z, v1.w);
    uint32_t h1 = f2h2(v2.x, v2.y);
    uint32_t h3 = f2h2(v2.z, v2.w);
    uint32_t h5 = f2h2(v3.x, v3.y);
    uint32_t h7 = f2h2(v3.z, v3.w);
    uint4 o0, o1;
    o0.x = h0; o0.y = h1; o0.z = h2; o0.w = h3;
    o1.x = h4; o1.y = h5; o1.z = h6; o1.w = h7;
    out[2 * i] = o0; out[2 * i + 1] = o1;
}

__global__ __launch_bounds__(256)
void cvt_x_k(const float4* __restrict__ in, uint4* __restrict__ out) {
    size_t i = (size_t)blockIdx.x * 256 + threadIdx.x;
    cvt_perm16(in, out, i);
}

__global__ __launch_bounds__(256)
void cvt_w_k(const float4* __restrict__ w0, uint4* __restrict__ o0,
             const float4* __restrict__ w1, uint4* __restrict__ o1,
             const float4* __restrict__ w2, uint4* __restrict__ o2,
             const float4* __restrict__ w3, uint4* __restrict__ o3) {
    const int seg = blockIdx.x >> 8;
    const size_t i = (size_t)(blockIdx.x & 255) * 256 + threadIdx.x;
    const float4* in  = (seg == 0) ? w0 : (seg == 1) ? w1 : (seg == 2) ? w2 : w3;
    uint4*        out = (seg == 0) ? o0 : (seg == 1) ? o1 : (seg == 2) ? o2 : o3;
    cvt_perm16(in, out, i);
}

__global__ __launch_bounds__(256)
void mask_flags_k(const int* __restrict__ mask) {
    const int q0 = blockIdx.x * 128, k0 = blockIdx.y * 64;
    const int t = threadIdx.x;
    const int row = q0 + (t >> 1);
    const int4* p = (const int4*)(mask + (size_t)row * SEQ + k0 + (t & 1) * 32);
    int ok = 1;
    #pragma unroll
    for (int j = 0; j < 8; j++) {
        int4 v = p[j];
        ok &= (v.x != 0) & (v.y != 0) & (v.z != 0) & (v.w != 0);
    }
    ok = __all_sync(0xffffffffu, ok);
    __shared__ int ws[8];
    if ((t & 31) == 0) ws[t >> 5] = ok;
    __syncthreads();
    if (t == 0) {
        int f = 1;
        #pragma unroll
        for (int j = 0; j < 8; j++) f &= ws[j];
        g_Mflag[blockIdx.x * (SEQ / 64) + blockIdx.y] = f;
    }
}

// ====== fp16 HMMA GEMM: CTA 128x256, warp tile 64x64, XOR-swizzled rows ======
#define NCHUNK   16
#define GROWB    128
#define GTILEA   (128 * GROWB)              // 16384
#define GTILEB2  (256 * GROWB)              // 32768
#define GSTAGEB  (GTILEA + GTILEB2)         // 49152
#define GEMM_SMEM (3 * GSTAGEB)             // 147456

__device__ __forceinline__ void gemm_main16(const __half* __restrict__ A,
                                            const __half* __restrict__ W,
                                            char* smc, int m0, int n0,
                                            float acc[4][8][4]) {
    const int t = threadIdx.x;
    const int lane = t & 31, wid = t >> 5;
    const int wm = wid & 1, wn = wid >> 1;     // 2(M) x 4(N), warp tile 64x64
    const int g = lane >> 2, tq = lane & 3;
    const int sel = g & 3;

    const int lrow = t >> 3;                 // 0..31
    const int lseg = t & 7;
    const int phys = csw8(lseg, lrow);
    const __half* Agp = A + (size_t)(m0 + lrow) * D_MODEL + lseg * 8;
    const __half* Wgp = W + (size_t)(n0 + lrow) * D_MODEL + lseg * 8;
    const uint32_t sA0 = smem_u32(smc) + (uint32_t)(lrow * GROWB + phys * 16);

    auto load_chunk = [&](int ic) {
        const int s = ic % 3;
        const uint32_t da = sA0 + s * GSTAGEB;
        const uint32_t db = da + GTILEA;
        const __half* ga = Agp + ic * 64;
        const __half* gb = Wgp + ic * 64;
        #pragma unroll
        for (int j = 0; j < 4; j++)
            CP_ASYNC16(da + j * 32 * GROWB, (const void*)(ga + (size_t)j * 32 * D_MODEL));
        #pragma unroll
        for (int j = 0; j < 8; j++)
            CP_ASYNC16(db + j * 32 * GROWB, (const void*)(gb + (size_t)j * 32 * D_MODEL));
        CP_COMMIT();
    };

    load_chunk(0);
    load_chunk(1);

    const int arow = wm * 64 + g;
    const int brow = wn * 64 + g;

    for (int i = 0; i < NCHUNK; i++) {
        if (i + 1 < NCHUNK) { CP_WAIT1(); } else { CP_WAIT0(); }
        __syncthreads();
        if (i + 2 < NCHUNK) load_chunk(i + 2);

        const char* As = smc + (i % 3) * GSTAGEB;
        const char* Bs = As + GTILEA;

        #pragma unroll
        for (int kb = 0; kb < 4; kb++) {
            const int off = ((kb ^ sel) << 5) + tq * 8;
            uint32_t a[4][4], b[8][2];
            #pragma unroll
            for (int mi = 0; mi < 4; mi++) {
                const uint2 lo = *(const uint2*)(As + (arow + mi * 16) * GROWB + off);
                const uint2 hi = *(const uint2*)(As + (arow + mi * 16 + 8) * GROWB + off);
                a[mi][0] = lo.x; a[mi][2] = lo.y;
                a[mi][1] = hi.x; a[mi][3] = hi.y;
            }
            #pragma unroll
            for (int ni = 0; ni < 8; ni++) {
                const uint2 bb = *(const uint2*)(Bs + (brow + ni * 8) * GROWB + off);
                b[ni][0] = bb.x; b[ni][1] = bb.y;
            }
            #pragma unroll
            for (int mi = 0; mi < 4; mi++)
                #pragma unroll
                for (int ni = 0; ni < 8; ni++)
                    mma_f16(acc[mi][ni], a[mi][0], a[mi][1], a[mi][2], a[mi][3],
                            b[ni][0], b[ni][1]);
        }
    }
}

// Fused Q/K/V projections (CTA tile 128x256)
__global__ __launch_bounds__(256, 1)
void gemm_qkv(const __half* __restrict__ X,
              const __half* __restrict__ Wq, const float* __restrict__ bq, __half* __restrict__ Q,
              const __half* __restrict__ Wk, const float* __restrict__ bk, __half* __restrict__ K,
              const __half* __restrict__ Wv, const float* __restrict__ bv, __half* __restrict__ V) {
    extern __shared__ char smc[];
    const int z = blockIdx.z;
    const __half* W    = (z == 0) ? Wq : (z == 1) ? Wk : Wv;
    const float*  bias = (z == 0) ? bq : (z == 1) ? bk : bv;
    __half*       C    = (z == 0) ? Q  : (z == 1) ? K  : V;

    const int m0 = blockIdx.y * 128, n0 = blockIdx.x * 256;
    float acc[4][8][4];
    #pragma unroll
    for (int mi = 0; mi < 4; mi++)
        #pragma unroll
        for (int ni = 0; ni < 8; ni++)
            #pragma unroll
            for (int r = 0; r < 4; r++) acc[mi][ni][r] = 0.f;

    gemm_main16(X, W, smc, m0, n0, acc);

    const int t = threadIdx.x;
    const int lane = t & 31, wid = t >> 5;
    const int wm = wid & 1, wn = wid >> 1;
    const int g = lane >> 2, tq = lane & 3;

    #pragma unroll
    for (int mi = 0; mi < 4; mi++) {
        #pragma unroll
        for (int ni = 0; ni < 8; ni++) {
            const int n = n0 + wn * 64 + ni * 8 + 2 * tq;
            const float2 bv2 = *(const float2*)&bias[n];
            #pragma unroll
            for (int rr = 0; rr < 2; rr++) {
                const int m = m0 + wm * 64 + mi * 16 + g + rr * 8;
                float vx = acc[mi][ni][rr * 2 + 0] + bv2.x;
                float vy = acc[mi][ni][rr * 2 + 1] + bv2.y;
                const int b_ = m / SEQ, s_ = m % SEQ;
                const int h_ = n / D_KH, dk = n % D_KH;
                if (z == 0) { vx *= 0.18033688f; vy *= 0.18033688f; }
                if (z == 2) {
                    const int sp = (s_ & ~15) + perm16(s_ & 15);
                    __half* baseV = C + ((size_t)((b_ * N_HEADS + h_) * D_KH + dk)) * SEQ;
                    baseV[sp] = __float2half_rn(vx);
                    baseV[SEQ + sp] = __float2half_rn(vy);
                } else {
                    const int grp = dk & ~15;
                    const int pos = p8((dk & 15) >> 1) * 2;
                    __half* base = C + (((size_t)(b_ * N_HEADS + h_)) * SEQ + s_) * D_KH + grp + pos;
                    *(uint32_t*)base = f2h2(vx, vy);
                }
            }
        }
    }
}

// Output projection (CTA tile 128x256): fp16 in, fp32 out row-major
__global__ __launch_bounds__(256, 1)
void gemm_out(const __half* __restrict__ A, const __half* __restrict__ W,
              const float* __restrict__ bias, float* __restrict__ C) {
    extern __shared__ char smc[];
    const int m0 = blockIdx.y * 128, n0 = blockIdx.x * 256;
    float acc[4][8][4];
    #pragma unroll
    for (int mi = 0; mi < 4; mi++)
        #pragma unroll
        for (int ni = 0; ni < 8; ni++)
            #pragma unroll
            for (int r = 0; r < 4; r++) acc[mi][ni][r] = 0.f;

    gemm_main16(A, W, smc, m0, n0, acc);

    const int t = threadIdx.x;
    const int lane = t & 31, wid = t >> 5;
    const int wm = wid & 1, wn = wid >> 1;
    const int g = lane >> 2, tq = lane & 3;

    #pragma unroll
    for (int mi = 0; mi < 4; mi++) {
        #pragma unroll
        for (int ni = 0; ni < 8; ni++) {
            const int n = n0 + wn * 64 + ni * 8 + 2 * tq;
            const float2 bv2 = *(const float2*)&bias[n];
            #pragma unroll
            for (int rr = 0; rr < 2; rr++) {
                const int m = m0 + wm * 64 + mi * 16 + g + rr * 8;
                float2 v;
                v.x = acc[mi][ni][rr * 2 + 0] + bv2.x;
                v.y = acc[mi][ni][rr * 2 + 1] + bv2.y;
                *(float2*)(C + (size_t)m * D_MODEL + n) = v;
            }
        }
    }
}

// ============ fp16 flash attention (m16n8k16, 128q x 64k) ====================
#define AROWB 128
#define AKB   (64 * AROWB)                   // 8192
#define AKAVB (2 * AKB)                      // 16384
#define ATTN_SMEM (3 * AKAVB)                // 49152
#define NKT (SEQ / 64)

__global__ __launch_bounds__(128)
void attn_kernel(const int* __restrict__ mask) {
    extern __shared__ char smc[];
    const uint32_t sb = smem_u32(smc);
    const int t = threadIdx.x;
    const int lane = t & 31, wid = t >> 5;
    const int g = lane >> 2, tq = lane & 3;
    const int sel = g & 3;
    const int q0 = blockIdx.x * 128;
    const int bh = blockIdx.y;
    const int b = bh / N_HEADS, h = bh % N_HEADS;

    const __half* Qg = g_Q16 + (size_t)bh * SEQ * D_KH;
    const __half* Kg = g_K16 + (size_t)bh * SEQ * D_KH;
    const __half* Vg = g_V16 + (size_t)bh * D_KH * SEQ;
    const int* Mfl = g_Mflag + (q0 >> 7) * (SEQ / 64);

    #pragma unroll
    for (int j = 0; j < 8; j++) {
        const int u = t + j * 128;
        const int row = u >> 3, seg = u & 7;
        *(uint4*)(smc + row * AROWB + csw8(seg, row) * 16) =
            *(const uint4*)(Qg + (size_t)(q0 + row) * D_KH + seg * 8);
    }
    __syncthreads();

    const int wq = wid * 32;
    uint32_t qf[2][4][4];
    #pragma unroll
    for (int blk = 0; blk < 2; blk++) {
        #pragma unroll
        for (int kb = 0; kb < 4; kb++) {
            const int off = ((kb ^ sel) << 5) + tq * 8;
            const char* qp = smc + (wq + blk * 16 + g) * AROWB + off;
            const uint2 lo = *(const uint2*)qp;
            const uint2 hi = *(const uint2*)(qp + 8 * AROWB);
            qf[blk][kb][0] = lo.x; qf[blk][kb][2] = lo.y;
            qf[blk][kb][1] = hi.x; qf[blk][kb][3] = hi.y;
        }
    }
    __syncthreads();

    auto load_kv = [&](int ik) {
        const int s = ik % 3;
        const uint32_t kb = sb + s * AKAVB;
        const uint32_t vb = kb + AKB;
        const int krow0 = ik * 64;
        #pragma unroll
        for (int j = 0; j < 4; j++) {
            const int u = t + j * 128;
            const int row = u >> 3, seg = u & 7;
            const uint32_t so = (uint32_t)(row * AROWB + csw8(seg, row) * 16);
            CP_ASYNC16(kb + so, (const void*)(Kg + (size_t)(krow0 + row) * D_KH + seg * 8));
            CP_ASYNC16(vb + so, (const void*)(Vg + (size_t)row * SEQ + krow0 + seg * 8));
        }
        CP_COMMIT();
    };

    load_kv(0);
    load_kv(1);

    float oT[2][4][2][4];
    #pragma unroll
    for (int blk = 0; blk < 2; blk++)
        #pragma unroll
        for (int dkb = 0; dkb < 4; dkb++)
            #pragma unroll
            for (int hf = 0; hf < 2; hf++)
                #pragma unroll
                for (int r = 0; r < 4; r++) oT[blk][dkb][hf][r] = 0.f;
    float l[2][2] = {{0.f, 0.f}, {0.f, 0.f}};

    for (int ik = 0; ik < NKT; ik++) {
        if (ik + 1 < NKT) { CP_WAIT1(); } else { CP_WAIT0(); }
        __syncthreads();
        if (ik + 2 < NKT) load_kv(ik + 2);

        const char* Ks = smc + (ik % 3) * AKAVB;
        const char* Vs = Ks + AKB;

        float s[2][8][4];
        #pragma unroll
        for (int blk = 0; blk < 2; blk++)
            #pragma unroll
            for (int ni = 0; ni < 8; ni++)
                #pragma unroll
                for (int r = 0; r < 4; r++) s[blk][ni][r] = 0.f;

        #pragma unroll
        for (int kb = 0; kb < 4; kb++) {
            const int off = ((kb ^ sel) << 5) + tq * 8;
            #pragma unroll
            for (int ni = 0; ni < 8; ni++) {
                const uint2 kv2 = *(const uint2*)(Ks + (ni * 8 + g) * AROWB + off);
                mma_f16(s[0][ni], qf[0][kb][0], qf[0][kb][1], qf[0][kb][2], qf[0][kb][3],
                        kv2.x, kv2.y);
                mma_f16(s[1][ni], qf[1][kb][0], qf[1][kb][1], qf[1][kb][2], qf[1][kb][3],
                        kv2.x, kv2.y);
            }
        }

        if (!Mfl[ik]) {
            const int kcol = ik * 64 + 2 * tq;
            #pragma unroll
            for (int blk = 0; blk < 2; blk++) {
                const int mrow = q0 + wq + blk * 16 + g;
                #pragma unroll
                for (int ni = 0; ni < 8; ni++) {
                    const int2 mv0 = *(const int2*)&mask[(size_t)mrow * SEQ + kcol + ni * 8];
                    const int2 mv1 = *(const int2*)&mask[(size_t)(mrow + 8) * SEQ + kcol + ni * 8];
                    if (!mv0.x) s[blk][ni][0] = -1e30f;
                    if (!mv0.y) s[blk][ni][1] = -1e30f;
                    if (!mv1.x) s[blk][ni][2] = -1e30f;
                    if (!mv1.y) s[blk][ni][3] = -1e30f;
                }
            }
        }

        #pragma unroll
        for (int blk = 0; blk < 2; blk++) {
            #pragma unroll
            for (int ni = 0; ni < 8; ni++) {
                s[blk][ni][0] = ex2f(s[blk][ni][0]);
                s[blk][ni][1] = ex2f(s[blk][ni][1]);
                s[blk][ni][2] = ex2f(s[blk][ni][2]);
                s[blk][ni][3] = ex2f(s[blk][ni][3]);
                l[blk][0] += s[blk][ni][0] + s[blk][ni][1];
                l[blk][1] += s[blk][ni][2] + s[blk][ni][3];
            }
        }

        #pragma unroll
        for (int j = 0; j < 4; j++) {
            const int off = ((j ^ sel) << 5) + tq * 8;
            uint32_t pb[2][2][2];
            #pragma unroll
            for (int blk = 0; blk < 2; blk++) {
                pb[blk][0][0] = f2h2(s[blk][2*j][0],   s[blk][2*j][1]);
                pb[blk][0][1] = f2h2(s[blk][2*j+1][0], s[blk][2*j+1][1]);
                pb[blk][1][0] = f2h2(s[blk][2*j][2],   s[blk][2*j][3]);
                pb[blk][1][1] = f2h2(s[blk][2*j+1][2], s[blk][2*j+1][3]);
            }
            #pragma unroll
            for (int dkb = 0; dkb < 4; dkb++) {
                const uint2 lo = *(const uint2*)(Vs + (dkb * 16 + g) * AROWB + off);
                const uint2 hi = *(const uint2*)(Vs + (dkb * 16 + g + 8) * AROWB + off);
                mma_f16(oT[0][dkb][0], lo.x, hi.x, lo.y, hi.y, pb[0][0][0], pb[0][0][1]);
                mma_f16(oT[0][dkb][1], lo.x, hi.x, lo.y, hi.y, pb[0][1][0], pb[0][1][1]);
                mma_f16(oT[1][dkb][0], lo.x, hi.x, lo.y, hi.y, pb[1][0][0], pb[1][0][1]);
                mma_f16(oT[1][dkb][1], lo.x, hi.x, lo.y, hi.y, pb[1][1][0], pb[1][1][1]);
            }
        }
    }

    const int pos_g = p8(g >> 1) * 2 + (g & 1);
    #pragma unroll
    for (int blk = 0; blk < 2; blk++) {
        float l0 = l[blk][0], l1 = l[blk][1];
        l0 += __shfl_xor_sync(0xffffffffu, l0, 1);
        l0 += __shfl_xor_sync(0xffffffffu, l0, 2);
        l1 += __shfl_xor_sync(0xffffffffu, l1, 1);
        l1 += __shfl_xor_sync(0xffffffffu, l1, 2);
        const float lA = __shfl_sync(0xffffffffu, l0, 8 * tq);
        const float lB = __shfl_sync(0xffffffffu, l0, 8 * tq + 4);
        const float lC = __shfl_sync(0xffffffffu, l1, 8 * tq);
        const float lD = __shfl_sync(0xffffffffu, l1, 8 * tq + 4);
        const float iA = 1.0f / lA, iB = 1.0f / lB, iC = 1.0f / lC, iD = 1.0f / lD;

        const int rA = q0 + wq + blk * 16 + 2 * tq;
        __half* OA = g_O16 + (size_t)(b * SEQ + rA)     * D_MODEL + h * D_KH;
        __half* OB = g_O16 + (size_t)(b * SEQ + rA + 1) * D_MODEL + h * D_KH;
        __half* OC = g_O16 + (size_t)(b * SEQ + rA + 8) * D_MODEL + h * D_KH;
        __half* OD = g_O16 + (size_t)(b * SEQ + rA + 9) * D_MODEL + h * D_KH;
        #pragma unroll
        for (int dkb = 0; dkb < 4; dkb++) {
            const int c1 = dkb * 16 + pos_g;
            const int c2 = c1 + 2;
            OA[c1] = __float2half_rn(oT[blk][dkb][0][0] * iA);
            OB[c1] = __float2half_rn(oT[blk][dkb][0][1] * iB);
            OA[c2] = __float2half_rn(oT[blk][dkb][0][2] * iA);
            OB[c2] = __float2half_rn(oT[blk][dkb][0][3] * iB);
            OC[c1] = __float2half_rn(oT[blk][dkb][1][0] * iC);
            OD[c1] = __float2half_rn(oT[blk][dkb][1][1] * iD);
            OC[c2] = __float2half_rn(oT[blk][dkb][1][2] * iC);
            OD[c2] = __float2half_rn(oT[blk][dkb][1][3] * iD);
        }
    }
}

// ---------------- launch -----------------------------------------------------
extern "C" void kernel_launch(void* const* d_in, const int* in_sizes, int n_in,
                              void* d_out, int out_size) {
    (void)in_sizes; (void)n_in; (void)out_size;
    const float* x    = (const float*)d_in[0];
    const int*   mask = (const int*)  d_in[1];
    const float* wq   = (const float*)d_in[2];
    const float* bq   = (const float*)d_in[3];
    const float* wk   = (const float*)d_in[4];
    const float* bk   = (const float*)d_in[5];
    const float* wv   = (const float*)d_in[6];
    const float* bv   = (const float*)d_in[7];
    const float* wo   = (const float*)d_in[8];
    const float* bo   = (const float*)d_in[9];
    float* out = (float*)d_out;

    __half *dQ, *dK, *dV, *dO, *dX, *dWq, *dWk, *dWv, *dWo;
    cudaGetSymbolAddress((void**)&dQ,  g_Q16);
    cudaGetSymbolAddress((void**)&dK,  g_K16);
    cudaGetSymbolAddress((void**)&dV,  g_V16);
    cudaGetSymbolAddress((void**)&dO,  g_O16);
    cudaGetSymbolAddress((void**)&dX,  g_X16);
    cudaGetSymbolAddress((void**)&dWq, g_Wq16);
    cudaGetSymbolAddress((void**)&dWk, g_Wk16);
    cudaGetSymbolAddress((void**)&dWv, g_Wv16);
    cudaGetSymbolAddress((void**)&dWo, g_Wo16);

    cudaFuncSetAttribute(gemm_qkv, cudaFuncAttributeMaxDynamicSharedMemorySize, GEMM_SMEM);
    cudaFuncSetAttribute(gemm_out, cudaFuncAttributeMaxDynamicSharedMemorySize, GEMM_SMEM);
    cudaFuncSetAttribute(attn_kernel, cudaFuncAttributeMaxDynamicSharedMemorySize, ATTN_SMEM);

    // prepass
    cvt_x_k<<<2048, 256>>>((const float4*)x, (uint4*)dX);
    cvt_w_k<<<1024, 256>>>((const float4*)wq, (uint4*)dWq,
                           (const float4*)wk, (uint4*)dWk,
                           (const float4*)wv, (uint4*)dWv,
                           (const float4*)wo, (uint4*)dWo);
    mask_flags_k<<<dim3(SEQ/128, SEQ/64), 256>>>(mask);

    // fused Q/K/V projections (CTA 128x256)
    gemm_qkv<<<dim3(D_MODEL/256, MROWS/128, 3), 256, GEMM_SMEM>>>(
        dX, dWq, bq, dQ, dWk, bk, dK, dWv, bv, dV);

    attn_kernel<<<dim3(SEQ/128, BATCH*N_HEADS), 128, ATTN_SMEM>>>(mask);

    gemm_out<<<dim3(D_MODEL/256, MROWS/128), 256, GEMM_SMEM>>>(dO, dWo, bo, out);
}

// round 17
// speedup vs baseline: 1.0682x; 1.0682x over previous
#include <cuda_runtime.h>
#include <cuda_fp16.h>
#include <math.h>
#include <cstdint>

#define D_MODEL 1024
#define N_HEADS 16
#define D_KH    64
#define BATCH   4
#define SEQ     2048
#define MROWS   (BATCH*SEQ)   // 8192

// ---------------- scratch (device globals: allocation-free rule) ------------
__device__ __half g_Q16[(size_t)BATCH*N_HEADS*SEQ*D_KH];
__device__ __half g_K16[(size_t)BATCH*N_HEADS*SEQ*D_KH];
__device__ __half g_V16[(size_t)BATCH*N_HEADS*SEQ*D_KH];
__device__ __half g_O16[(size_t)MROWS*D_MODEL];
__device__ __half g_X16[(size_t)MROWS*D_MODEL];
__device__ __half g_Wq16[(size_t)D_MODEL*D_MODEL];
__device__ __half g_Wk16[(size_t)D_MODEL*D_MODEL];
__device__ __half g_Wv16[(size_t)D_MODEL*D_MODEL];
__device__ __half g_Wo16[(size_t)D_MODEL*D_MODEL];
__device__ int    g_Mflag[(SEQ/128)*(SEQ/64)];

// =============================== PTX helpers ================================
__device__ __forceinline__ uint32_t smem_u32(const void* p) {
    uint32_t a;
    asm("{ .reg .u64 t; cvta.to.shared.u64 t, %1; cvt.u32.u64 %0, t; }" : "=r"(a) : "l"(p));
    return a;
}
__device__ __forceinline__ float ex2f(float x) {
    float y;
    asm("ex2.approx.f32 %0, %1;" : "=f"(y) : "f"(x));
    return y;
}
__device__ __forceinline__ uint32_t f2h2(float lo, float hi) {
    uint32_t r;
    asm("cvt.rn.f16x2.f32 %0, %2, %1;" : "=r"(r) : "f"(lo), "f"(hi));
    return r;
}
__device__ __forceinline__ void mma_f16(float* c,
                                        uint32_t a0, uint32_t a1, uint32_t a2, uint32_t a3,
                                        uint32_t b0, uint32_t b1) {
    asm volatile(
        "mma.sync.aligned.m16n8k16.row.col.f32.f16.f16.f32 "
        "{%0,%1,%2,%3}, {%4,%5,%6,%7}, {%8,%9}, {%0,%1,%2,%3};"
        : "+f"(c[0]), "+f"(c[1]), "+f"(c[2]), "+f"(c[3])
        : "r"(a0), "r"(a1), "r"(a2), "r"(a3), "r"(b0), "r"(b1));
}
#define CP_ASYNC16(sa, ga) \
    asm volatile("cp.async.cg.shared.global [%0], [%1], 16;" :: "r"(sa), "l"(ga) : "memory")
#define CP_COMMIT() asm volatile("cp.async.commit_group;" ::: "memory")
#define CP_WAIT1()  asm volatile("cp.async.wait_group 1;" ::: "memory")
#define CP_WAIT0()  asm volatile("cp.async.wait_group 0;" ::: "memory")

__device__ __forceinline__ int p8(int p) { return (p < 4) ? 2 * p : 2 * (p - 4) + 1; }
__device__ __forceinline__ int perm16(int d) { return p8(d >> 1) * 2 + (d & 1); }
__device__ __forceinline__ int csw8(int c, int r) {
    return (((c >> 1) ^ (r & 3)) << 1) | (c & 1);
}

// ---------------- prepass kernels -------------------------------------------
__device__ __forceinline__ void cvt_perm16(const float4* in, uint4* out, size_t i) {
    float4 v0 = in[4 * i], v1 = in[4 * i + 1], v2 = in[4 * i + 2], v3 = in[4 * i + 3];
    uint32_t h0 = f2h2(v0.x, v0.y);
    uint32_t h2 = f2h2(v0.z, v0.w);
    uint32_t h4 = f2h2(v1.x, v1.y);
    uint32_t h6 = f2h2(v1.z, v1.w);
    uint32_t h1 = f2h2(v2.x, v2.y);
    uint32_t h3 = f2h2(v2.z, v2.w);
    uint32_t h5 = f2h2(v3.x, v3.y);
    uint32_t h7 = f2h2(v3.z, v3.w);
    uint4 o0, o1;
    o0.x = h0; o0.y = h1; o0.z = h2; o0.w = h3;
    o1.x = h4; o1.y = h5; o1.z = h6; o1.w = h7;
    out[2 * i] = o0; out[2 * i + 1] = o1;
}

__global__ __launch_bounds__(256)
void cvt_x_k(const float4* __restrict__ in, uint4* __restrict__ out) {
    size_t i = (size_t)blockIdx.x * 256 + threadIdx.x;
    cvt_perm16(in, out, i);
}

__global__ __launch_bounds__(256)
void cvt_w_k(const float4* __restrict__ w0, uint4* __restrict__ o0,
             const float4* __restrict__ w1, uint4* __restrict__ o1,
             const float4* __restrict__ w2, uint4* __restrict__ o2,
             const float4* __restrict__ w3, uint4* __restrict__ o3) {
    const int seg = blockIdx.x >> 8;
    const size_t i = (size_t)(blockIdx.x & 255) * 256 + threadIdx.x;
    const float4* in  = (seg == 0) ? w0 : (seg == 1) ? w1 : (seg == 2) ? w2 : w3;
    uint4*        out = (seg == 0) ? o0 : (seg == 1) ? o1 : (seg == 2) ? o2 : o3;
    cvt_perm16(in, out, i);
}

__global__ __launch_bounds__(256)
void mask_flags_k(const int* __restrict__ mask) {
    const int q0 = blockIdx.x * 128, k0 = blockIdx.y * 64;
    const int t = threadIdx.x;
    const int row = q0 + (t >> 1);
    const int4* p = (const int4*)(mask + (size_t)row * SEQ + k0 + (t & 1) * 32);
    int ok = 1;
    #pragma unroll
    for (int j = 0; j < 8; j++) {
        int4 v = p[j];
        ok &= (v.x != 0) & (v.y != 0) & (v.z != 0) & (v.w != 0);
    }
    ok = __all_sync(0xffffffffu, ok);
    __shared__ int ws[8];
    if ((t & 31) == 0) ws[t >> 5] = ok;
    __syncthreads();
    if (t == 0) {
        int f = 1;
        #pragma unroll
        for (int j = 0; j < 8; j++) f &= ws[j];
        g_Mflag[blockIdx.x * (SEQ / 64) + blockIdx.y] = f;
    }
}

// == fp16 HMMA GEMM: CTA 128x128, 128 thr (2x2 warps, 64x64 tile), 2 CTAs/SM ==
#define NCHUNK   16
#define GROWB    128
#define GTILEB   (128 * GROWB)              // 16384
#define GSTAGEB  (2 * GTILEB)               // 32768
#define GEMM_SMEM (3 * GSTAGEB)             // 98304

__device__ __forceinline__ void gemm_main16(const __half* __restrict__ A,
                                            const __half* __restrict__ W,
                                            char* smc, int m0, int n0,
                                            float acc[4][8][4]) {
    const int t = threadIdx.x;
    const int lane = t & 31, wid = t >> 5;   // 4 warps
    const int wm = wid & 1, wn = wid >> 1;   // 2(M) x 2(N), warp tile 64x64
    const int g = lane >> 2, tq = lane & 3;
    const int sel = g & 3;

    const int lrow = t >> 3;                 // 0..15
    const int lseg = t & 7;
    const int phys = csw8(lseg, lrow);
    const __half* Agp = A + (size_t)(m0 + lrow) * D_MODEL + lseg * 8;
    const __half* Wgp = W + (size_t)(n0 + lrow) * D_MODEL + lseg * 8;
    const uint32_t sA0 = smem_u32(smc) + (uint32_t)(lrow * GROWB + phys * 16);

    auto load_chunk = [&](int ic) {
        const int s = ic % 3;
        const uint32_t da = sA0 + s * GSTAGEB;
        const uint32_t db = da + GTILEB;
        const __half* ga = Agp + ic * 64;
        const __half* gb = Wgp + ic * 64;
        #pragma unroll
        for (int j = 0; j < 8; j++) {        // rows advance by 16: swizzle-invariant
            CP_ASYNC16(da + j * 16 * GROWB, (const void*)(ga + (size_t)j * 16 * D_MODEL));
            CP_ASYNC16(db + j * 16 * GROWB, (const void*)(gb + (size_t)j * 16 * D_MODEL));
        }
        CP_COMMIT();
    };

    load_chunk(0);
    load_chunk(1);

    const int arow = wm * 64 + g;
    const int brow = wn * 64 + g;

    for (int i = 0; i < NCHUNK; i++) {
        if (i + 1 < NCHUNK) { CP_WAIT1(); } else { CP_WAIT0(); }
        __syncthreads();
        if (i + 2 < NCHUNK) load_chunk(i + 2);

        const char* As = smc + (i % 3) * GSTAGEB;
        const char* Bs = As + GTILEB;

        #pragma unroll
        for (int kb = 0; kb < 4; kb++) {
            const int off = ((kb ^ sel) << 5) + tq * 8;
            uint32_t a[4][4], b[8][2];
            #pragma unroll
            for (int mi = 0; mi < 4; mi++) {
                const uint2 lo = *(const uint2*)(As + (arow + mi * 16) * GROWB + off);
                const uint2 hi = *(const uint2*)(As + (arow + mi * 16 + 8) * GROWB + off);
                a[mi][0] = lo.x; a[mi][2] = lo.y;
                a[mi][1] = hi.x; a[mi][3] = hi.y;
            }
            #pragma unroll
            for (int ni = 0; ni < 8; ni++) {
                const uint2 bb = *(const uint2*)(Bs + (brow + ni * 8) * GROWB + off);
                b[ni][0] = bb.x; b[ni][1] = bb.y;
            }
            #pragma unroll
            for (int mi = 0; mi < 4; mi++)
                #pragma unroll
                for (int ni = 0; ni < 8; ni++)
                    mma_f16(acc[mi][ni], a[mi][0], a[mi][1], a[mi][2], a[mi][3],
                            b[ni][0], b[ni][1]);
        }
    }
}

// Fused Q/K/V projections (CTA 128x128, 128 threads)
__global__ __launch_bounds__(128, 2)
void gemm_qkv(const __half* __restrict__ X,
              const __half* __restrict__ Wq, const float* __restrict__ bq, __half* __restrict__ Q,
              const __half* __restrict__ Wk, const float* __restrict__ bk, __half* __restrict__ K,
              const __half* __restrict__ Wv, const float* __restrict__ bv, __half* __restrict__ V) {
    extern __shared__ char smc[];
    const int z = blockIdx.z;
    const __half* W    = (z == 0) ? Wq : (z == 1) ? Wk : Wv;
    const float*  bias = (z == 0) ? bq : (z == 1) ? bk : bv;
    __half*       C    = (z == 0) ? Q  : (z == 1) ? K  : V;

    const int m0 = blockIdx.y * 128, n0 = blockIdx.x * 128;
    float acc[4][8][4];
    #pragma unroll
    for (int mi = 0; mi < 4; mi++)
        #pragma unroll
        for (int ni = 0; ni < 8; ni++)
            #pragma unroll
            for (int r = 0; r < 4; r++) acc[mi][ni][r] = 0.f;

    gemm_main16(X, W, smc, m0, n0, acc);

    const int t = threadIdx.x;
    const int lane = t & 31, wid = t >> 5;
    const int wm = wid & 1, wn = wid >> 1;
    const int g = lane >> 2, tq = lane & 3;

    #pragma unroll
    for (int mi = 0; mi < 4; mi++) {
        #pragma unroll
        for (int ni = 0; ni < 8; ni++) {
            const int n = n0 + wn * 64 + ni * 8 + 2 * tq;
            const float2 bv2 = *(const float2*)&bias[n];
            #pragma unroll
            for (int rr = 0; rr < 2; rr++) {
                const int m = m0 + wm * 64 + mi * 16 + g + rr * 8;
                float vx = acc[mi][ni][rr * 2 + 0] + bv2.x;
                float vy = acc[mi][ni][rr * 2 + 1] + bv2.y;
                const int b_ = m / SEQ, s_ = m % SEQ;
                const int h_ = n / D_KH, dk = n % D_KH;
                if (z == 0) { vx *= 0.18033688f; vy *= 0.18033688f; }
                if (z == 2) {
                    const int sp = (s_ & ~15) + perm16(s_ & 15);
                    __half* baseV = C + ((size_t)((b_ * N_HEADS + h_) * D_KH + dk)) * SEQ;
                    baseV[sp] = __float2half_rn(vx);
                    baseV[SEQ + sp] = __float2half_rn(vy);
                } else {
                    const int grp = dk & ~15;
                    const int pos = p8((dk & 15) >> 1) * 2;
                    __half* base = C + (((size_t)(b_ * N_HEADS + h_)) * SEQ + s_) * D_KH + grp + pos;
                    *(uint32_t*)base = f2h2(vx, vy);
                }
            }
        }
    }
}

// Output projection (CTA 128x128, 128 threads): fp16 in, fp32 out
__global__ __launch_bounds__(128, 2)
void gemm_out(const __half* __restrict__ A, const __half* __restrict__ W,
              const float* __restrict__ bias, float* __restrict__ C) {
    extern __shared__ char smc[];
    const int m0 = blockIdx.y * 128, n0 = blockIdx.x * 128;
    float acc[4][8][4];
    #pragma unroll
    for (int mi = 0; mi < 4; mi++)
        #pragma unroll
        for (int ni = 0; ni < 8; ni++)
            #pragma unroll
            for (int r = 0; r < 4; r++) acc[mi][ni][r] = 0.f;

    gemm_main16(A, W, smc, m0, n0, acc);

    const int t = threadIdx.x;
    const int lane = t & 31, wid = t >> 5;
    const int wm = wid & 1, wn = wid >> 1;
    const int g = lane >> 2, tq = lane & 3;

    #pragma unroll
    for (int mi = 0; mi < 4; mi++) {
        #pragma unroll
        for (int ni = 0; ni < 8; ni++) {
            const int n = n0 + wn * 64 + ni * 8 + 2 * tq;
            const float2 bv2 = *(const float2*)&bias[n];
            #pragma unroll
            for (int rr = 0; rr < 2; rr++) {
                const int m = m0 + wm * 64 + mi * 16 + g + rr * 8;
                float2 v;
                v.x = acc[mi][ni][rr * 2 + 0] + bv2.x;
                v.y = acc[mi][ni][rr * 2 + 1] + bv2.y;
                *(float2*)(C + (size_t)m * D_MODEL + n) = v;
            }
        }
    }
}

// ============ fp16 flash attention (m16n8k16, 128q x 64k) — R15 best =========
#define AROWB 128
#define AKB   (64 * AROWB)                   // 8192
#define AKAVB (2 * AKB)                      // 16384
#define ATTN_SMEM (3 * AKAVB)                // 49152
#define NKT (SEQ / 64)

__global__ __launch_bounds__(128)
void attn_kernel(const int* __restrict__ mask) {
    extern __shared__ char smc[];
    const uint32_t sb = smem_u32(smc);
    const int t = threadIdx.x;
    const int lane = t & 31, wid = t >> 5;
    const int g = lane >> 2, tq = lane & 3;
    const int sel = g & 3;
    const int q0 = blockIdx.x * 128;
    const int bh = blockIdx.y;
    const int b = bh / N_HEADS, h = bh % N_HEADS;

    const __half* Qg = g_Q16 + (size_t)bh * SEQ * D_KH;
    const __half* Kg = g_K16 + (size_t)bh * SEQ * D_KH;
    const __half* Vg = g_V16 + (size_t)bh * D_KH * SEQ;
    const int* Mfl = g_Mflag + (q0 >> 7) * (SEQ / 64);

    #pragma unroll
    for (int j = 0; j < 8; j++) {
        const int u = t + j * 128;
        const int row = u >> 3, seg = u & 7;
        *(uint4*)(smc + row * AROWB + csw8(seg, row) * 16) =
            *(const uint4*)(Qg + (size_t)(q0 + row) * D_KH + seg * 8);
    }
    __syncthreads();

    const int wq = wid * 32;
    uint32_t qf[2][4][4];
    #pragma unroll
    for (int blk = 0; blk < 2; blk++) {
        #pragma unroll
        for (int kb = 0; kb < 4; kb++) {
            const int off = ((kb ^ sel) << 5) + tq * 8;
            const char* qp = smc + (wq + blk * 16 + g) * AROWB + off;
            const uint2 lo = *(const uint2*)qp;
            const uint2 hi = *(const uint2*)(qp + 8 * AROWB);
            qf[blk][kb][0] = lo.x; qf[blk][kb][2] = lo.y;
            qf[blk][kb][1] = hi.x; qf[blk][kb][3] = hi.y;
        }
    }
    __syncthreads();

    auto load_kv = [&](int ik) {
        const int s = ik % 3;
        const uint32_t kb = sb + s * AKAVB;
        const uint32_t vb = kb + AKB;
        const int krow0 = ik * 64;
        #pragma unroll
        for (int j = 0; j < 4; j++) {
            const int u = t + j * 128;
            const int row = u >> 3, seg = u & 7;
            const uint32_t so = (uint32_t)(row * AROWB + csw8(seg, row) * 16);
            CP_ASYNC16(kb + so, (const void*)(Kg + (size_t)(krow0 + row) * D_KH + seg * 8));
            CP_ASYNC16(vb + so, (const void*)(Vg + (size_t)row * SEQ + krow0 + seg * 8));
        }
        CP_COMMIT();
    };

    load_kv(0);
    load_kv(1);

    float oT[2][4][2][4];
    #pragma unroll
    for (int blk = 0; blk < 2; blk++)
        #pragma unroll
        for (int dkb = 0; dkb < 4; dkb++)
            #pragma unroll
            for (int hf = 0; hf < 2; hf++)
                #pragma unroll
                for (int r = 0; r < 4; r++) oT[blk][dkb][hf][r] = 0.f;
    float l[2][2] = {{0.f, 0.f}, {0.f, 0.f}};

    for (int ik = 0; ik < NKT; ik++) {
        if (ik + 1 < NKT) { CP_WAIT1(); } else { CP_WAIT0(); }
        __syncthreads();
        if (ik + 2 < NKT) load_kv(ik + 2);

        const char* Ks = smc + (ik % 3) * AKAVB;
        const char* Vs = Ks + AKB;

        float s[2][8][4];
        #pragma unroll
        for (int blk = 0; blk < 2; blk++)
            #pragma unroll
            for (int ni = 0; ni < 8; ni++)
                #pragma unroll
                for (int r = 0; r < 4; r++) s[blk][ni][r] = 0.f;

        #pragma unroll
        for (int kb = 0; kb < 4; kb++) {
            const int off = ((kb ^ sel) << 5) + tq * 8;
            #pragma unroll
            for (int ni = 0; ni < 8; ni++) {
                const uint2 kv2 = *(const uint2*)(Ks + (ni * 8 + g) * AROWB + off);
                mma_f16(s[0][ni], qf[0][kb][0], qf[0][kb][1], qf[0][kb][2], qf[0][kb][3],
                        kv2.x, kv2.y);
                mma_f16(s[1][ni], qf[1][kb][0], qf[1][kb][1], qf[1][kb][2], qf[1][kb][3],
                        kv2.x, kv2.y);
            }
        }

        if (!Mfl[ik]) {
            const int kcol = ik * 64 + 2 * tq;
            #pragma unroll
            for (int blk = 0; blk < 2; blk++) {
                const int mrow = q0 + wq + blk * 16 + g;
                #pragma unroll
                for (int ni = 0; ni < 8; ni++) {
                    const int2 mv0 = *(const int2*)&mask[(size_t)mrow * SEQ + kcol + ni * 8];
                    const int2 mv1 = *(const int2*)&mask[(size_t)(mrow + 8) * SEQ + kcol + ni * 8];
                    if (!mv0.x) s[blk][ni][0] = -1e30f;
                    if (!mv0.y) s[blk][ni][1] = -1e30f;
                    if (!mv1.x) s[blk][ni][2] = -1e30f;
                    if (!mv1.y) s[blk][ni][3] = -1e30f;
                }
            }
        }

        #pragma unroll
        for (int blk = 0; blk < 2; blk++) {
            #pragma unroll
            for (int ni = 0; ni < 8; ni++) {
                s[blk][ni][0] = ex2f(s[blk][ni][0]);
                s[blk][ni][1] = ex2f(s[blk][ni][1]);
                s[blk][ni][2] = ex2f(s[blk][ni][2]);
                s[blk][ni][3] = ex2f(s[blk][ni][3]);
                l[blk][0] += s[blk][ni][0] + s[blk][ni][1];
                l[blk][1] += s[blk][ni][2] + s[blk][ni][3];
            }
        }

        #pragma unroll
        for (int j = 0; j < 4; j++) {
            const int off = ((j ^ sel) << 5) + tq * 8;
            uint32_t pb[2][2][2];
            #pragma unroll
            for (int blk = 0; blk < 2; blk++) {
                pb[blk][0][0] = f2h2(s[blk][2*j][0],   s[blk][2*j][1]);
                pb[blk][0][1] = f2h2(s[blk][2*j+1][0], s[blk][2*j+1][1]);
                pb[blk][1][0] = f2h2(s[blk][2*j][2],   s[blk][2*j][3]);
                pb[blk][1][1] = f2h2(s[blk][2*j+1][2], s[blk][2*j+1][3]);
            }
            #pragma unroll
            for (int dkb = 0; dkb < 4; dkb++) {
                const uint2 lo = *(const uint2*)(Vs + (dkb * 16 + g) * AROWB + off);
                const uint2 hi = *(const uint2*)(Vs + (dkb * 16 + g + 8) * AROWB + off);
                mma_f16(oT[0][dkb][0], lo.x, hi.x, lo.y, hi.y, pb[0][0][0], pb[0][0][1]);
                mma_f16(oT[0][dkb][1], lo.x, hi.x, lo.y, hi.y, pb[0][1][0], pb[0][1][1]);
                mma_f16(oT[1][dkb][0], lo.x, hi.x, lo.y, hi.y, pb[1][0][0], pb[1][0][1]);
                mma_f16(oT[1][dkb][1], lo.x, hi.x, lo.y, hi.y, pb[1][1][0], pb[1][1][1]);
            }
        }
    }

    const int pos_g = p8(g >> 1) * 2 + (g & 1);
    #pragma unroll
    for (int blk = 0; blk < 2; blk++) {
        float l0 = l[blk][0], l1 = l[blk][1];
        l0 += __shfl_xor_sync(0xffffffffu, l0, 1);
        l0 += __shfl_xor_sync(0xffffffffu, l0, 2);
        l1 += __shfl_xor_sync(0xffffffffu, l1, 1);
        l1 += __shfl_xor_sync(0xffffffffu, l1, 2);
        const float lA = __shfl_sync(0xffffffffu, l0, 8 * tq);
        const float lB = __shfl_sync(0xffffffffu, l0, 8 * tq + 4);
        const float lC = __shfl_sync(0xffffffffu, l1, 8 * tq);
        const float lD = __shfl_sync(0xffffffffu, l1, 8 * tq + 4);
        const float iA = 1.0f / lA, iB = 1.0f / lB, iC = 1.0f / lC, iD = 1.0f / lD;

        const int rA = q0 + wq + blk * 16 + 2 * tq;
        __half* OA = g_O16 + (size_t)(b * SEQ + rA)     * D_MODEL + h * D_KH;
        __half* OB = g_O16 + (size_t)(b * SEQ + rA + 1) * D_MODEL + h * D_KH;
        __half* OC = g_O16 + (size_t)(b * SEQ + rA + 8) * D_MODEL + h * D_KH;
        __half* OD = g_O16 + (size_t)(b * SEQ + rA + 9) * D_MODEL + h * D_KH;
        #pragma unroll
        for (int dkb = 0; dkb < 4; dkb++) {
            const int c1 = dkb * 16 + pos_g;
            const int c2 = c1 + 2;
            OA[c1] = __float2half_rn(oT[blk][dkb][0][0] * iA);
            OB[c1] = __float2half_rn(oT[blk][dkb][0][1] * iB);
            OA[c2] = __float2half_rn(oT[blk][dkb][0][2] * iA);
            OB[c2] = __float2half_rn(oT[blk][dkb][0][3] * iB);
            OC[c1] = __float2half_rn(oT[blk][dkb][1][0] * iC);
            OD[c1] = __float2half_rn(oT[blk][dkb][1][1] * iD);
            OC[c2] = __float2half_rn(oT[blk][dkb][1][2] * iC);
            OD[c2] = __float2half_rn(oT[blk][dkb][1][3] * iD);
        }
    }
}

// ---------------- launch -----------------------------------------------------
extern "C" void kernel_launch(void* const* d_in, const int* in_sizes, int n_in,
                              void* d_out, int out_size) {
    (void)in_sizes; (void)n_in; (void)out_size;
    const float* x    = (const float*)d_in[0];
    const int*   mask = (const int*)  d_in[1];
    const float* wq   = (const float*)d_in[2];
    const float* bq   = (const float*)d_in[3];
    const float* wk   = (const float*)d_in[4];
    const float* bk   = (const float*)d_in[5];
    const float* wv   = (const float*)d_in[6];
    const float* bv   = (const float*)d_in[7];
    const float* wo   = (const float*)d_in[8];
    const float* bo   = (const float*)d_in[9];
    float* out = (float*)d_out;

    __half *dQ, *dK, *dV, *dO, *dX, *dWq, *dWk, *dWv, *dWo;
    cudaGetSymbolAddress((void**)&dQ,  g_Q16);
    cudaGetSymbolAddress((void**)&dK,  g_K16);
    cudaGetSymbolAddress((void**)&dV,  g_V16);
    cudaGetSymbolAddress((void**)&dO,  g_O16);
    cudaGetSymbolAddress((void**)&dX,  g_X16);
    cudaGetSymbolAddress((void**)&dWq, g_Wq16);
    cudaGetSymbolAddress((void**)&dWk, g_Wk16);
    cudaGetSymbolAddress((void**)&dWv, g_Wv16);
    cudaGetSymbolAddress((void**)&dWo, g_Wo16);

    cudaFuncSetAttribute(gemm_qkv, cudaFuncAttributeMaxDynamicSharedMemorySize, GEMM_SMEM);
    cudaFuncSetAttribute(gemm_out, cudaFuncAttributeMaxDynamicSharedMemorySize, GEMM_SMEM);
    cudaFuncSetAttribute(attn_kernel, cudaFuncAttributeMaxDynamicSharedMemorySize, ATTN_SMEM);

    // prepass
    cvt_x_k<<<2048, 256>>>((const float4*)x, (uint4*)dX);
    cvt_w_k<<<1024, 256>>>((const float4*)wq, (uint4*)dWq,
                           (const float4*)wk, (uint4*)dWk,
                           (const float4*)wv, (uint4*)dWv,
                           (const float4*)wo, (uint4*)dWo);
    mask_flags_k<<<dim3(SEQ/128, SEQ/64), 256>>>(mask);

    // fused Q/K/V projections (CTA 128x128, 128 threads)
    gemm_qkv<<<dim3(D_MODEL/128, MROWS/128, 3), 128, GEMM_SMEM>>>(
        dX, dWq, bq, dQ, dWk, bk, dK, dWv, bv, dV);

    attn_kernel<<<dim3(SEQ/128, BATCH*N_HEADS), 128, ATTN_SMEM>>>(mask);

    gemm_out<<<dim3(D_MODEL/128, MROWS/128), 128, GEMM_SMEM>>>(dO, dWo, bo, out);
}